// round 13
// baseline (speedup 1.0000x reference)
#include <cuda_runtime.h>
#include <math.h>
#include <stdint.h>

#define BB 32
#define HH 32
#define DM 4096
#define DK 128
#define SINK 4
#define WINDOW 1020
#define MAXC (SINK + WINDOW)   // 1024

// ---------------- device scratch (no allocs allowed) ----------------
__device__ float g_ctx [BB * DM];
__device__ float g_part[48 * BB * DM];  // QKV: 3 x 16 slabs; O: 32 slabs
__device__ float g_cos[MAXC * 64];
__device__ float g_sin[MAXC * 64];
__device__ float g_pm  [2 * BB * HH];
__device__ float g_pl  [2 * BB * HH];
__device__ float g_pacc[2 * BB * HH * DK];

// ---------------- helpers ----------------
__device__ __forceinline__ void cpa16(uint32_t dst, const void* src) {
    asm volatile("cp.async.cg.shared.global [%0], [%1], 16;" :: "r"(dst), "l"(src));
}
__device__ __forceinline__ uint32_t f2tf(float f) {
    uint32_t u;
    asm("cvt.rna.tf32.f32 %0, %1;" : "=r"(u) : "f"(f));
    return u;
}
__device__ __forceinline__ void mma8(float* d, const uint32_t* a, const uint32_t* b) {
    asm volatile("mma.sync.aligned.m16n8k8.row.col.f32.tf32.tf32.f32 "
                 "{%0,%1,%2,%3}, {%4,%5,%6,%7}, {%8,%9}, {%0,%1,%2,%3};"
                 : "+f"(d[0]), "+f"(d[1]), "+f"(d[2]), "+f"(d[3])
                 : "r"(a[0]), "r"(a[1]), "r"(a[2]), "r"(a[3]), "r"(b[0]), "r"(b[1]));
}

// ---------------- RoPE cos/sin table: pos in [0,1024), j in [0,64) ----------------
__global__ void rope_table_kernel() {
    int idx = blockIdx.x * 256 + threadIdx.x;   // 65536 entries
    int pos = idx >> 6;
    int j   = idx & 63;
    float theta = powf(10000.0f, -(float)j / 64.0f);
    float m = (float)pos * theta;
    float s, c;
    sincosf(m, &s, &c);
    g_cos[idx] = c;
    g_sin[idx] = s;
}

// ---------------- tf32 MMA GEMM: out[b][n] = sum_k X[b][k] * W[n][k] ----------------
// grid (DM/128, nWeights, ksplit). block 256 thr (8 warps). Warp owns 16 n.
#define GCK 32
#define WP  36
#define NPB 128
#define KSQ 16
#define KSO 32

__global__ void __launch_bounds__(256) mma_gemm_kernel(
                                   const float* __restrict__ X,
                                   const float* __restrict__ W0,
                                   const float* __restrict__ W1,
                                   const float* __restrict__ W2,
                                   int klen)
{
    __shared__ float ws[2][NPB * WP];
    __shared__ float xs[2][BB * WP];
    const float* Xp = X ? X : g_ctx;
    const float* W  = (blockIdx.y == 0) ? W0 : (blockIdx.y == 1) ? W1 : W2;
    const int tid   = threadIdx.x;
    const int lane  = tid & 31;
    const int warp  = tid >> 5;
    const int gid   = lane >> 2;     // 0..7
    const int tig   = lane & 3;      // 0..3
    const int n0    = warp * 16;
    const int nbase = blockIdx.x * NPB;
    const int kbase = blockIdx.z * klen;
    const int ntiles = klen / GCK;

    const uint32_t ws_b = (uint32_t)__cvta_generic_to_shared(&ws[0][0]);
    const uint32_t xs_b = (uint32_t)__cvta_generic_to_shared(&xs[0][0]);
    const uint32_t ws_sz = NPB * WP * 4;
    const uint32_t xs_sz = BB * WP * 4;

    auto stage = [&](int t) {
        const int buf = t & 1;
        const int k0 = kbase + t * GCK;
#pragma unroll
        for (int i = 0; i < 4; i++) {
            int idx = tid + i * 256;
            int r = idx >> 3, c2 = idx & 7;
            cpa16(ws_b + buf * ws_sz + (r * WP + 4 * c2) * 4,
                  &W[(size_t)(nbase + r) * DM + k0 + 4 * c2]);
        }
        {
            int r = tid >> 3, c2 = tid & 7;
            cpa16(xs_b + buf * xs_sz + (r * WP + 4 * c2) * 4,
                  &Xp[(size_t)r * DM + k0 + 4 * c2]);
        }
        asm volatile("cp.async.commit_group;");
    };

    float d[4][4];
#pragma unroll
    for (int i = 0; i < 4; i++)
#pragma unroll
        for (int j = 0; j < 4; j++) d[i][j] = 0.0f;

    stage(0);
    for (int t = 0; t < ntiles; t++) {
        if (t + 1 < ntiles) {
            stage(t + 1);
            asm volatile("cp.async.wait_group 1;");
        } else {
            asm volatile("cp.async.wait_group 0;");
        }
        __syncthreads();

        const int buf = t & 1;
        const float* xb = &xs[buf][0];
        const float* wb = &ws[buf][0];
#pragma unroll
        for (int k8 = 0; k8 < 4; k8++) {
            const int kk = k8 * 8;
            uint32_t A0[4], A1[4], B0[2], B1[2];
            A0[0] = f2tf(xb[(gid)      * WP + kk + tig]);
            A0[1] = f2tf(xb[(gid + 8)  * WP + kk + tig]);
            A0[2] = f2tf(xb[(gid)      * WP + kk + tig + 4]);
            A0[3] = f2tf(xb[(gid + 8)  * WP + kk + tig + 4]);
            A1[0] = f2tf(xb[(gid + 16) * WP + kk + tig]);
            A1[1] = f2tf(xb[(gid + 24) * WP + kk + tig]);
            A1[2] = f2tf(xb[(gid + 16) * WP + kk + tig + 4]);
            A1[3] = f2tf(xb[(gid + 24) * WP + kk + tig + 4]);
            B0[0] = f2tf(wb[(n0 + gid)     * WP + kk + tig]);
            B0[1] = f2tf(wb[(n0 + gid)     * WP + kk + tig + 4]);
            B1[0] = f2tf(wb[(n0 + 8 + gid) * WP + kk + tig]);
            B1[1] = f2tf(wb[(n0 + 8 + gid) * WP + kk + tig + 4]);
            mma8(d[0], A0, B0);
            mma8(d[1], A0, B1);
            mma8(d[2], A1, B0);
            mma8(d[3], A1, B1);
        }
        __syncthreads();
    }

    const int slab = (blockIdx.y * gridDim.z + blockIdx.z) * (BB * DM);
#pragma unroll
    for (int mi = 0; mi < 2; mi++)
#pragma unroll
        for (int ni = 0; ni < 2; ni++) {
            const float* dd = d[mi * 2 + ni];
            int ncol = nbase + n0 + ni * 8 + 2 * tig;
            int brow = gid + mi * 16;
            *(float2*)&g_part[slab + (size_t)brow * DM + ncol]       = make_float2(dd[0], dd[1]);
            *(float2*)&g_part[slab + (size_t)(brow + 8) * DM + ncol] = make_float2(dd[2], dd[3]);
        }
}

// reduce 32 k-split partials for the output projection into d_out
__global__ void o_reduce_kernel(float* __restrict__ out) {
    int i = blockIdx.x * 256 + threadIdx.x;   // 131072
    float v = 0.0f;
#pragma unroll
    for (int z = 0; z < KSO; z++) v += g_part[(size_t)z * (BB * DM) + i];
    out[i] = v;
}

// ---------------- attention: interleaved split x2; QKV partial-reduce fused in prologue ----------------
__global__ void __launch_bounds__(256) attn_kernel(
                            const float* __restrict__ kcache,
                            const float* __restrict__ vcache,
                            const int* __restrict__ seqp)
{
    __shared__ __align__(16) float s_qr[DK];
    __shared__ __align__(16) float s_kn[DK];
    __shared__ __align__(16) float s_vn[DK];
    __shared__ float s_m[8];
    __shared__ float s_l[8];
    __shared__ float s_acc[8][DK + 4];

    const int h = blockIdx.x, b = blockIdx.y, z = blockIdx.z;
    const int tid  = threadIdx.x;
    const int lane = tid & 31;
    const int warp = tid >> 5;

    const int seq = *seqp;
    int L, ii;
    if (seq < MAXC) { L = seq + 1; ii = seq; }
    else            { L = MAXC;    ii = SINK + (seq - SINK) % WINDOW; }
    const int qpos = L - 1;
    const int bh = b * HH + h;

    // ---- prologue: reduce this (b,h)'s Q/K/V rows from the GEMM k-split partials ----
    if (tid < DK) {
        const size_t base = (size_t)b * DM + h * DK + tid;
        float vq = 0.0f, vk = 0.0f, vv = 0.0f;
#pragma unroll
        for (int zz = 0; zz < KSQ; zz++) {
            const size_t off = (size_t)zz * (BB * DM) + base;
            vq += g_part[off];
            vk += g_part[off + (size_t)(KSQ)     * (BB * DM)];
            vv += g_part[off + (size_t)(2 * KSQ) * (BB * DM)];
        }
        s_kn[tid] = vk;
        s_vn[tid] = vv;
        s_qr[tid] = vq;
    }
    __syncthreads();
    if (tid < DK) {
        int j = tid & 63;
        float q0 = s_qr[tid];
        float flip = (tid < 64) ? -s_qr[tid + 64] : s_qr[tid - 64];
        float c = g_cos[qpos * 64 + j];
        float s = g_sin[qpos * 64 + j];
        s_acc[0][tid] = (q0 * c + flip * s) * 0.08838834764831843f;  // staging
    }
    __syncthreads();
    if (tid < DK) s_qr[tid] = s_acc[0][tid];
    __syncthreads();

    const float4 q4 = ((const float4*)s_qr)[lane];
    const float  sgn = (lane < 16) ? -1.0f : 1.0f;
    const int    j16 = lane & 15;
    const float* kbp  = kcache + (size_t)bh * MAXC * DK;
    const float* vbp  = vcache + (size_t)bh * MAXC * DK;

    // ---- init online softmax; block z=0 warp 0 seeds with the inserted slot (RoPE pos == qpos) ----
    float m, l;
    float4 a;
    if (warp == 0 && z == 0) {
        float4 kn = ((const float4*)s_kn)[lane];
        float4 vn = ((const float4*)s_vn)[lane];
        float4 cs = ((const float4*)(g_cos + qpos * 64))[j16];
        float4 sn = ((const float4*)(g_sin + qpos * 64))[j16];
        float fx = sgn * __shfl_xor_sync(0xffffffffu, kn.x, 16);
        float fy = sgn * __shfl_xor_sync(0xffffffffu, kn.y, 16);
        float fz = sgn * __shfl_xor_sync(0xffffffffu, kn.z, 16);
        float fw = sgn * __shfl_xor_sync(0xffffffffu, kn.w, 16);
        float d = q4.x * (kn.x * cs.x + fx * sn.x) + q4.y * (kn.y * cs.y + fy * sn.y)
                + q4.z * (kn.z * cs.z + fz * sn.z) + q4.w * (kn.w * cs.w + fw * sn.w);
#pragma unroll
        for (int o = 16; o; o >>= 1) d += __shfl_xor_sync(0xffffffffu, d, o);
        m = d; l = 1.0f; a = vn;
    } else {
        m = -1e30f; l = 0.0f; a = make_float4(0.f, 0.f, 0.f, 0.f);
    }

    // interleaved split: 16 global warp-slots, this block covers slots warp + z*8
    int c = warp + z * 8;
    for (; c + 16 < L; c += 32) {
        const int cA = c, cB = c + 16;
        float4 kA = __ldcs((const float4*)(kbp + (size_t)cA * DK) + lane);
        float4 kB = __ldcs((const float4*)(kbp + (size_t)cB * DK) + lane);
        float4 vA = __ldcs((const float4*)(vbp + (size_t)cA * DK) + lane);
        float4 vB = __ldcs((const float4*)(vbp + (size_t)cB * DK) + lane);
        int pA, pB;
        if (seq < MAXC) { pA = cA; pB = cB; }
        else {
            pA = (cA < SINK) ? cA : (cA > ii) ? (SINK + cA - ii - 1) : (cA + (MAXC - 1 - ii));
            pB = (cB < SINK) ? cB : (cB > ii) ? (SINK + cB - ii - 1) : (cB + (MAXC - 1 - ii));
        }
        float4 csA = ((const float4*)(g_cos + pA * 64))[j16];
        float4 snA = ((const float4*)(g_sin + pA * 64))[j16];
        float4 csB = ((const float4*)(g_cos + pB * 64))[j16];
        float4 snB = ((const float4*)(g_sin + pB * 64))[j16];
        float dA, dB;
        {
            float fx = sgn * __shfl_xor_sync(0xffffffffu, kA.x, 16);
            float fy = sgn * __shfl_xor_sync(0xffffffffu, kA.y, 16);
            float fz = sgn * __shfl_xor_sync(0xffffffffu, kA.z, 16);
            float fw = sgn * __shfl_xor_sync(0xffffffffu, kA.w, 16);
            dA = q4.x * (kA.x * csA.x + fx * snA.x) + q4.y * (kA.y * csA.y + fy * snA.y)
               + q4.z * (kA.z * csA.z + fz * snA.z) + q4.w * (kA.w * csA.w + fw * snA.w);
        }
        {
            float fx = sgn * __shfl_xor_sync(0xffffffffu, kB.x, 16);
            float fy = sgn * __shfl_xor_sync(0xffffffffu, kB.y, 16);
            float fz = sgn * __shfl_xor_sync(0xffffffffu, kB.z, 16);
            float fw = sgn * __shfl_xor_sync(0xffffffffu, kB.w, 16);
            dB = q4.x * (kB.x * csB.x + fx * snB.x) + q4.y * (kB.y * csB.y + fy * snB.y)
               + q4.z * (kB.z * csB.z + fz * snB.z) + q4.w * (kB.w * csB.w + fw * snB.w);
        }
#pragma unroll
        for (int o = 16; o; o >>= 1) {
            dA += __shfl_xor_sync(0xffffffffu, dA, o);
            dB += __shfl_xor_sync(0xffffffffu, dB, o);
        }
        const bool skA = (cA == ii), skB = (cB == ii);
        if (skA) dA = -1e30f;
        if (skB) dB = -1e30f;
        float mn = fmaxf(m, fmaxf(dA, dB));
        float sc = __expf(m - mn);
        float eA = skA ? 0.0f : __expf(dA - mn);
        float eB = skB ? 0.0f : __expf(dB - mn);
        l = l * sc + eA + eB;
        a.x = a.x * sc + eA * vA.x + eB * vB.x;
        a.y = a.y * sc + eA * vA.y + eB * vB.y;
        a.z = a.z * sc + eA * vA.z + eB * vB.z;
        a.w = a.w * sc + eA * vA.w + eB * vB.w;
        m = mn;
    }
    for (; c < L; c += 16) {
        float4 kv = __ldcs((const float4*)(kbp + (size_t)c * DK) + lane);
        float4 vv = __ldcs((const float4*)(vbp + (size_t)c * DK) + lane);
        int pos;
        if (seq < MAXC) pos = c;
        else pos = (c < SINK) ? c
                 : (c > ii)   ? (SINK + c - ii - 1)
                              : (c + (MAXC - 1 - ii));
        float4 cs = ((const float4*)(g_cos + pos * 64))[j16];
        float4 sn = ((const float4*)(g_sin + pos * 64))[j16];
        float fx = sgn * __shfl_xor_sync(0xffffffffu, kv.x, 16);
        float fy = sgn * __shfl_xor_sync(0xffffffffu, kv.y, 16);
        float fz = sgn * __shfl_xor_sync(0xffffffffu, kv.z, 16);
        float fw = sgn * __shfl_xor_sync(0xffffffffu, kv.w, 16);
        float d = q4.x * (kv.x * cs.x + fx * sn.x) + q4.y * (kv.y * cs.y + fy * sn.y)
                + q4.z * (kv.z * cs.z + fz * sn.z) + q4.w * (kv.w * cs.w + fw * sn.w);
#pragma unroll
        for (int o = 16; o; o >>= 1) d += __shfl_xor_sync(0xffffffffu, d, o);
        const bool sk = (c == ii);
        if (sk) d = -1e30f;
        float mn = fmaxf(m, d);
        float sc = __expf(m - mn);
        float e  = sk ? 0.0f : __expf(d - mn);
        l = l * sc + e;
        a.x = a.x * sc + e * vv.x;
        a.y = a.y * sc + e * vv.y;
        a.z = a.z * sc + e * vv.z;
        a.w = a.w * sc + e * vv.w;
        m = mn;
    }

    // ---- combine 8 warps; emit per-block partial (m, l, acc) ----
    if (lane == 0) { s_m[warp] = m; s_l[warp] = l; }
    *(float4*)&s_acc[warp][4 * lane] = a;
    __syncthreads();
    if (tid < DK) {
        float M = s_m[0];
#pragma unroll
        for (int w = 1; w < 8; w++) M = fmaxf(M, s_m[w]);
        float den = 0.0f, val = 0.0f;
#pragma unroll
        for (int w = 0; w < 8; w++) {
            float e = __expf(s_m[w] - M);
            den += e * s_l[w];
            val += e * s_acc[w][tid];
        }
        const int slot = bh * 2 + z;
        if (tid == 0) { g_pm[slot] = M; g_pl[slot] = den; }
        g_pacc[(size_t)slot * DK + tid] = val;
    }
}

// ---------------- combine the 2 split partials into the context ----------------
__global__ void attn_combine_kernel() {
    const int bh  = blockIdx.x;              // 0..1023
    const int tid = threadIdx.x;             // 0..127
    const int s0 = bh * 2, s1 = bh * 2 + 1;
    float m0 = g_pm[s0], m1 = g_pm[s1];
    float M  = fmaxf(m0, m1);
    float e0 = __expf(m0 - M), e1 = __expf(m1 - M);
    float den = e0 * g_pl[s0] + e1 * g_pl[s1];
    float val = e0 * g_pacc[(size_t)s0 * DK + tid] + e1 * g_pacc[(size_t)s1 * DK + tid];
    g_ctx[bh * DK + tid] = val / den;
}

// ---------------- launch ----------------
extern "C" void kernel_launch(void* const* d_in, const int* in_sizes, int n_in,
                              void* d_out, int out_size)
{
    const float* x_new   = (const float*)d_in[0];
    const float* k_cache = (const float*)d_in[1];
    const float* v_cache = (const float*)d_in[2];
    const float* W_Q     = (const float*)d_in[3];
    const float* W_K     = (const float*)d_in[4];
    const float* W_V     = (const float*)d_in[5];
    const float* W_O     = (const float*)d_in[6];
    const int*   seq_len = (const int*)  d_in[7];
    float* out = (float*)d_out;

    // 1. RoPE cos/sin table (1024 x 64)
    rope_table_kernel<<<256, 256>>>();

    // 2. QKV projections: tf32 MMA, 3 weights x 16 k-splits of 256 (partials only)
    mma_gemm_kernel<<<dim3(DM / NPB, 3, KSQ), 256>>>(x_new, W_Q, W_K, W_V, DM / KSQ);

    // 3. attention: interleaved split x2, QKV reduce fused in prologue; then combine
    attn_kernel<<<dim3(HH, BB, 2), 256>>>(k_cache, v_cache, seq_len);
    attn_combine_kernel<<<BB * HH, DK>>>();

    // 4. output projection: tf32 MMA, 1 weight x 32 k-splits of 128, reduce into d_out
    mma_gemm_kernel<<<dim3(DM / NPB, 1, KSO), 256>>>(nullptr, W_O, W_O, W_O, DM / KSO);
    o_reduce_kernel<<<(BB * DM) / 256, 256>>>(out);
}

// round 14
// speedup vs baseline: 1.0298x; 1.0298x over previous
#include <cuda_runtime.h>
#include <math.h>
#include <stdint.h>

#define BB 32
#define HH 32
#define DM 4096
#define DK 128
#define SINK 4
#define WINDOW 1020
#define MAXC (SINK + WINDOW)   // 1024

// ---------------- device scratch (no allocs allowed) ----------------
__device__ float g_ctx [BB * DM];
__device__ float g_part[48 * BB * DM];  // QKV: 3 x 16 slabs; O: 32 slabs
__device__ float g_cos[MAXC * 64];
__device__ float g_sin[MAXC * 64];

// ---------------- helpers ----------------
__device__ __forceinline__ void cpa16(uint32_t dst, const void* src) {
    asm volatile("cp.async.cg.shared.global [%0], [%1], 16;" :: "r"(dst), "l"(src));
}
__device__ __forceinline__ uint32_t f2tf(float f) {
    uint32_t u;
    asm("cvt.rna.tf32.f32 %0, %1;" : "=r"(u) : "f"(f));
    return u;
}
__device__ __forceinline__ void mma8(float* d, const uint32_t* a, const uint32_t* b) {
    asm volatile("mma.sync.aligned.m16n8k8.row.col.f32.tf32.tf32.f32 "
                 "{%0,%1,%2,%3}, {%4,%5,%6,%7}, {%8,%9}, {%0,%1,%2,%3};"
                 : "+f"(d[0]), "+f"(d[1]), "+f"(d[2]), "+f"(d[3])
                 : "r"(a[0]), "r"(a[1]), "r"(a[2]), "r"(a[3]), "r"(b[0]), "r"(b[1]));
}

// ---------------- RoPE cos/sin table: pos in [0,1024), j in [0,64) ----------------
__global__ void rope_table_kernel() {
    int idx = blockIdx.x * 256 + threadIdx.x;   // 65536 entries
    int pos = idx >> 6;
    int j   = idx & 63;
    float theta = powf(10000.0f, -(float)j / 64.0f);
    float m = (float)pos * theta;
    float s, c;
    sincosf(m, &s, &c);
    g_cos[idx] = c;
    g_sin[idx] = s;
}

// ---------------- tf32 MMA GEMM: out[b][n] = sum_k X[b][k] * W[n][k] ----------------
// grid (DM/128, nWeights, ksplit). block 256 thr (8 warps). Warp owns 16 n.
#define GCK 32
#define WP  36
#define NPB 128
#define KSQ 16
#define KSO 32

__global__ void __launch_bounds__(256) mma_gemm_kernel(
                                   const float* __restrict__ X,
                                   const float* __restrict__ W0,
                                   const float* __restrict__ W1,
                                   const float* __restrict__ W2,
                                   int klen)
{
    __shared__ float ws[2][NPB * WP];
    __shared__ float xs[2][BB * WP];
    const float* Xp = X ? X : g_ctx;
    const float* W  = (blockIdx.y == 0) ? W0 : (blockIdx.y == 1) ? W1 : W2;
    const int tid   = threadIdx.x;
    const int lane  = tid & 31;
    const int warp  = tid >> 5;
    const int gid   = lane >> 2;     // 0..7
    const int tig   = lane & 3;      // 0..3
    const int n0    = warp * 16;
    const int nbase = blockIdx.x * NPB;
    const int kbase = blockIdx.z * klen;
    const int ntiles = klen / GCK;

    const uint32_t ws_b = (uint32_t)__cvta_generic_to_shared(&ws[0][0]);
    const uint32_t xs_b = (uint32_t)__cvta_generic_to_shared(&xs[0][0]);
    const uint32_t ws_sz = NPB * WP * 4;
    const uint32_t xs_sz = BB * WP * 4;

    auto stage = [&](int t) {
        const int buf = t & 1;
        const int k0 = kbase + t * GCK;
#pragma unroll
        for (int i = 0; i < 4; i++) {
            int idx = tid + i * 256;
            int r = idx >> 3, c2 = idx & 7;
            cpa16(ws_b + buf * ws_sz + (r * WP + 4 * c2) * 4,
                  &W[(size_t)(nbase + r) * DM + k0 + 4 * c2]);
        }
        {
            int r = tid >> 3, c2 = tid & 7;
            cpa16(xs_b + buf * xs_sz + (r * WP + 4 * c2) * 4,
                  &Xp[(size_t)r * DM + k0 + 4 * c2]);
        }
        asm volatile("cp.async.commit_group;");
    };

    float d[4][4];
#pragma unroll
    for (int i = 0; i < 4; i++)
#pragma unroll
        for (int j = 0; j < 4; j++) d[i][j] = 0.0f;

    stage(0);
    for (int t = 0; t < ntiles; t++) {
        if (t + 1 < ntiles) {
            stage(t + 1);
            asm volatile("cp.async.wait_group 1;");
        } else {
            asm volatile("cp.async.wait_group 0;");
        }
        __syncthreads();

        const int buf = t & 1;
        const float* xb = &xs[buf][0];
        const float* wb = &ws[buf][0];
#pragma unroll
        for (int k8 = 0; k8 < 4; k8++) {
            const int kk = k8 * 8;
            uint32_t A0[4], A1[4], B0[2], B1[2];
            A0[0] = f2tf(xb[(gid)      * WP + kk + tig]);
            A0[1] = f2tf(xb[(gid + 8)  * WP + kk + tig]);
            A0[2] = f2tf(xb[(gid)      * WP + kk + tig + 4]);
            A0[3] = f2tf(xb[(gid + 8)  * WP + kk + tig + 4]);
            A1[0] = f2tf(xb[(gid + 16) * WP + kk + tig]);
            A1[1] = f2tf(xb[(gid + 24) * WP + kk + tig]);
            A1[2] = f2tf(xb[(gid + 16) * WP + kk + tig + 4]);
            A1[3] = f2tf(xb[(gid + 24) * WP + kk + tig + 4]);
            B0[0] = f2tf(wb[(n0 + gid)     * WP + kk + tig]);
            B0[1] = f2tf(wb[(n0 + gid)     * WP + kk + tig + 4]);
            B1[0] = f2tf(wb[(n0 + 8 + gid) * WP + kk + tig]);
            B1[1] = f2tf(wb[(n0 + 8 + gid) * WP + kk + tig + 4]);
            mma8(d[0], A0, B0);
            mma8(d[1], A0, B1);
            mma8(d[2], A1, B0);
            mma8(d[3], A1, B1);
        }
        __syncthreads();
    }

    const int slab = (blockIdx.y * gridDim.z + blockIdx.z) * (BB * DM);
#pragma unroll
    for (int mi = 0; mi < 2; mi++)
#pragma unroll
        for (int ni = 0; ni < 2; ni++) {
            const float* dd = d[mi * 2 + ni];
            int ncol = nbase + n0 + ni * 8 + 2 * tig;
            int brow = gid + mi * 16;
            *(float2*)&g_part[slab + (size_t)brow * DM + ncol]       = make_float2(dd[0], dd[1]);
            *(float2*)&g_part[slab + (size_t)(brow + 8) * DM + ncol] = make_float2(dd[2], dd[3]);
        }
}

// reduce 32 k-split partials for the output projection into d_out
__global__ void o_reduce_kernel(float* __restrict__ out) {
    int i = blockIdx.x * 256 + threadIdx.x;   // 131072
    float v = 0.0f;
#pragma unroll
    for (int z = 0; z < KSO; z++) v += g_part[(size_t)z * (BB * DM) + i];
    out[i] = v;
}

// ---------------- attention: one block per (b, h); QKV partial-reduce fused in prologue ----------------
__global__ void __launch_bounds__(256) attn_kernel(
                            const float* __restrict__ kcache,
                            const float* __restrict__ vcache,
                            const int* __restrict__ seqp)
{
    __shared__ __align__(16) float s_qr[DK];
    __shared__ __align__(16) float s_kn[DK];
    __shared__ __align__(16) float s_vn[DK];
    __shared__ float s_m[8];
    __shared__ float s_l[8];
    __shared__ float s_acc[8][DK + 4];

    const int h = blockIdx.x, b = blockIdx.y;
    const int tid  = threadIdx.x;
    const int lane = tid & 31;
    const int warp = tid >> 5;

    const int seq = *seqp;
    int L, ii;
    if (seq < MAXC) { L = seq + 1; ii = seq; }
    else            { L = MAXC;    ii = SINK + (seq - SINK) % WINDOW; }
    const int qpos = L - 1;
    const int bh = b * HH + h;

    // ---- prologue: reduce this (b,h)'s Q/K/V rows from the GEMM k-split partials ----
    if (tid < DK) {
        const size_t base = (size_t)b * DM + h * DK + tid;
        float vq = 0.0f, vk = 0.0f, vv = 0.0f;
#pragma unroll
        for (int z = 0; z < KSQ; z++) {
            const size_t off = (size_t)z * (BB * DM) + base;
            vq += g_part[off];
            vk += g_part[off + (size_t)(KSQ)     * (BB * DM)];
            vv += g_part[off + (size_t)(2 * KSQ) * (BB * DM)];
        }
        s_kn[tid] = vk;
        s_vn[tid] = vv;
        s_qr[tid] = vq;
    }
    __syncthreads();
    if (tid < DK) {
        int j = tid & 63;
        float q0 = s_qr[tid];
        float flip = (tid < 64) ? -s_qr[tid + 64] : s_qr[tid - 64];
        float c = g_cos[qpos * 64 + j];
        float s = g_sin[qpos * 64 + j];
        s_acc[0][tid] = (q0 * c + flip * s) * 0.08838834764831843f;  // staging
    }
    __syncthreads();
    if (tid < DK) s_qr[tid] = s_acc[0][tid];
    __syncthreads();

    const float4 q4 = ((const float4*)s_qr)[lane];
    const float  sgn = (lane < 16) ? -1.0f : 1.0f;
    const int    j16 = lane & 15;
    const float* kbp  = kcache + (size_t)bh * MAXC * DK;
    const float* vbp  = vcache + (size_t)bh * MAXC * DK;

    // ---- init online softmax; warp 0 seeds with the inserted slot (RoPE pos == qpos) ----
    float m, l;
    float4 a;
    if (warp == 0) {
        float4 kn = ((const float4*)s_kn)[lane];
        float4 vn = ((const float4*)s_vn)[lane];
        float4 cs = ((const float4*)(g_cos + qpos * 64))[j16];
        float4 sn = ((const float4*)(g_sin + qpos * 64))[j16];
        float fx = sgn * __shfl_xor_sync(0xffffffffu, kn.x, 16);
        float fy = sgn * __shfl_xor_sync(0xffffffffu, kn.y, 16);
        float fz = sgn * __shfl_xor_sync(0xffffffffu, kn.z, 16);
        float fw = sgn * __shfl_xor_sync(0xffffffffu, kn.w, 16);
        float d = q4.x * (kn.x * cs.x + fx * sn.x) + q4.y * (kn.y * cs.y + fy * sn.y)
                + q4.z * (kn.z * cs.z + fz * sn.z) + q4.w * (kn.w * cs.w + fw * sn.w);
#pragma unroll
        for (int o = 16; o; o >>= 1) d += __shfl_xor_sync(0xffffffffu, d, o);
        m = d; l = 1.0f; a = vn;
    } else {
        m = -1e30f; l = 0.0f; a = make_float4(0.f, 0.f, 0.f, 0.f);
    }

    int c = warp;
    for (; c + 8 < L; c += 16) {
        const int cA = c, cB = c + 8;
        float4 kA = __ldcs((const float4*)(kbp + (size_t)cA * DK) + lane);
        float4 kB = __ldcs((const float4*)(kbp + (size_t)cB * DK) + lane);
        float4 vA = __ldcs((const float4*)(vbp + (size_t)cA * DK) + lane);
        float4 vB = __ldcs((const float4*)(vbp + (size_t)cB * DK) + lane);
        int pA, pB;
        if (seq < MAXC) { pA = cA; pB = cB; }
        else {
            pA = (cA < SINK) ? cA : (cA > ii) ? (SINK + cA - ii - 1) : (cA + (MAXC - 1 - ii));
            pB = (cB < SINK) ? cB : (cB > ii) ? (SINK + cB - ii - 1) : (cB + (MAXC - 1 - ii));
        }
        float4 csA = ((const float4*)(g_cos + pA * 64))[j16];
        float4 snA = ((const float4*)(g_sin + pA * 64))[j16];
        float4 csB = ((const float4*)(g_cos + pB * 64))[j16];
        float4 snB = ((const float4*)(g_sin + pB * 64))[j16];
        float dA, dB;
        {
            float fx = sgn * __shfl_xor_sync(0xffffffffu, kA.x, 16);
            float fy = sgn * __shfl_xor_sync(0xffffffffu, kA.y, 16);
            float fz = sgn * __shfl_xor_sync(0xffffffffu, kA.z, 16);
            float fw = sgn * __shfl_xor_sync(0xffffffffu, kA.w, 16);
            dA = q4.x * (kA.x * csA.x + fx * snA.x) + q4.y * (kA.y * csA.y + fy * snA.y)
               + q4.z * (kA.z * csA.z + fz * snA.z) + q4.w * (kA.w * csA.w + fw * snA.w);
        }
        {
            float fx = sgn * __shfl_xor_sync(0xffffffffu, kB.x, 16);
            float fy = sgn * __shfl_xor_sync(0xffffffffu, kB.y, 16);
            float fz = sgn * __shfl_xor_sync(0xffffffffu, kB.z, 16);
            float fw = sgn * __shfl_xor_sync(0xffffffffu, kB.w, 16);
            dB = q4.x * (kB.x * csB.x + fx * snB.x) + q4.y * (kB.y * csB.y + fy * snB.y)
               + q4.z * (kB.z * csB.z + fz * snB.z) + q4.w * (kB.w * csB.w + fw * snB.w);
        }
#pragma unroll
        for (int o = 16; o; o >>= 1) {
            dA += __shfl_xor_sync(0xffffffffu, dA, o);
            dB += __shfl_xor_sync(0xffffffffu, dB, o);
        }
        const bool skA = (cA == ii), skB = (cB == ii);
        if (skA) dA = -1e30f;
        if (skB) dB = -1e30f;
        float mn = fmaxf(m, fmaxf(dA, dB));
        float sc = __expf(m - mn);
        float eA = skA ? 0.0f : __expf(dA - mn);
        float eB = skB ? 0.0f : __expf(dB - mn);
        l = l * sc + eA + eB;
        a.x = a.x * sc + eA * vA.x + eB * vB.x;
        a.y = a.y * sc + eA * vA.y + eB * vB.y;
        a.z = a.z * sc + eA * vA.z + eB * vB.z;
        a.w = a.w * sc + eA * vA.w + eB * vB.w;
        m = mn;
    }
    for (; c < L; c += 8) {
        float4 kv = __ldcs((const float4*)(kbp + (size_t)c * DK) + lane);
        float4 vv = __ldcs((const float4*)(vbp + (size_t)c * DK) + lane);
        int pos;
        if (seq < MAXC) pos = c;
        else pos = (c < SINK) ? c
                 : (c > ii)   ? (SINK + c - ii - 1)
                              : (c + (MAXC - 1 - ii));
        float4 cs = ((const float4*)(g_cos + pos * 64))[j16];
        float4 sn = ((const float4*)(g_sin + pos * 64))[j16];
        float fx = sgn * __shfl_xor_sync(0xffffffffu, kv.x, 16);
        float fy = sgn * __shfl_xor_sync(0xffffffffu, kv.y, 16);
        float fz = sgn * __shfl_xor_sync(0xffffffffu, kv.z, 16);
        float fw = sgn * __shfl_xor_sync(0xffffffffu, kv.w, 16);
        float d = q4.x * (kv.x * cs.x + fx * sn.x) + q4.y * (kv.y * cs.y + fy * sn.y)
                + q4.z * (kv.z * cs.z + fz * sn.z) + q4.w * (kv.w * cs.w + fw * sn.w);
#pragma unroll
        for (int o = 16; o; o >>= 1) d += __shfl_xor_sync(0xffffffffu, d, o);
        const bool sk = (c == ii);
        if (sk) d = -1e30f;
        float mn = fmaxf(m, d);
        float sc = __expf(m - mn);
        float e  = sk ? 0.0f : __expf(d - mn);
        l = l * sc + e;
        a.x = a.x * sc + e * vv.x;
        a.y = a.y * sc + e * vv.y;
        a.z = a.z * sc + e * vv.z;
        a.w = a.w * sc + e * vv.w;
        m = mn;
    }

    // ---- combine 8 warps ----
    if (lane == 0) { s_m[warp] = m; s_l[warp] = l; }
    *(float4*)&s_acc[warp][4 * lane] = a;
    __syncthreads();
    if (tid < DK) {
        float M = s_m[0];
#pragma unroll
        for (int w = 1; w < 8; w++) M = fmaxf(M, s_m[w]);
        float den = 0.0f, val = 0.0f;
#pragma unroll
        for (int w = 0; w < 8; w++) {
            float e = __expf(s_m[w] - M);
            den += e * s_l[w];
            val += e * s_acc[w][tid];
        }
        g_ctx[b * DM + h * DK + tid] = val / den;
    }
}

// ---------------- launch ----------------
extern "C" void kernel_launch(void* const* d_in, const int* in_sizes, int n_in,
                              void* d_out, int out_size)
{
    const float* x_new   = (const float*)d_in[0];
    const float* k_cache = (const float*)d_in[1];
    const float* v_cache = (const float*)d_in[2];
    const float* W_Q     = (const float*)d_in[3];
    const float* W_K     = (const float*)d_in[4];
    const float* W_V     = (const float*)d_in[5];
    const float* W_O     = (const float*)d_in[6];
    const int*   seq_len = (const int*)  d_in[7];
    float* out = (float*)d_out;

    // 1. RoPE cos/sin table (1024 x 64)
    rope_table_kernel<<<256, 256>>>();

    // 2. QKV projections: tf32 MMA, 3 weights x 16 k-splits of 256 (partials only)
    mma_gemm_kernel<<<dim3(DM / NPB, 3, KSQ), 256>>>(x_new, W_Q, W_K, W_V, DM / KSQ);

    // 3. attention: QKV partial-reduce fused into prologue; streams the window once
    attn_kernel<<<dim3(HH, BB), 256>>>(k_cache, v_cache, seq_len);

    // 4. output projection: tf32 MMA, 1 weight x 32 k-splits of 128, reduce into d_out
    mma_gemm_kernel<<<dim3(DM / NPB, 1, KSO), 256>>>(nullptr, W_O, W_O, W_O, DM / KSO);
    o_reduce_kernel<<<(BB * DM) / 256, 256>>>(out);
}

// round 15
// speedup vs baseline: 1.0483x; 1.0180x over previous
#include <cuda_runtime.h>
#include <math.h>
#include <stdint.h>

#define BB 32
#define HH 32
#define DM 4096
#define DK 128
#define SINK 4
#define WINDOW 1020
#define MAXC (SINK + WINDOW)   // 1024

// ---------------- device scratch (no allocs allowed) ----------------
__device__ float g_ctx [BB * DM];
__device__ float g_part[48 * BB * DM];  // QKV: 3 x 16 slabs; O: 32 slabs
__device__ float g_cos[MAXC * 64];
__device__ float g_sin[MAXC * 64];
__device__ float g_pm  [4 * BB * HH];
__device__ float g_pl  [4 * BB * HH];
__device__ float g_pacc[4 * BB * HH * DK];

// ---------------- helpers ----------------
__device__ __forceinline__ void cpa16(uint32_t dst, const void* src) {
    asm volatile("cp.async.cg.shared.global [%0], [%1], 16;" :: "r"(dst), "l"(src));
}
__device__ __forceinline__ uint32_t f2tf(float f) {
    uint32_t u;
    asm("cvt.rna.tf32.f32 %0, %1;" : "=r"(u) : "f"(f));
    return u;
}
__device__ __forceinline__ void mma8(float* d, const uint32_t* a, const uint32_t* b) {
    asm volatile("mma.sync.aligned.m16n8k8.row.col.f32.tf32.tf32.f32 "
                 "{%0,%1,%2,%3}, {%4,%5,%6,%7}, {%8,%9}, {%0,%1,%2,%3};"
                 : "+f"(d[0]), "+f"(d[1]), "+f"(d[2]), "+f"(d[3])
                 : "r"(a[0]), "r"(a[1]), "r"(a[2]), "r"(a[3]), "r"(b[0]), "r"(b[1]));
}

// ---------------- tf32 MMA GEMM: out[b][n] = sum_k X[b][k] * W[n][k] ----------------
// grid (DM/128, nWeights[+1 rope slice], ksplit). block 256 thr (8 warps). Warp owns 16 n.
// blockIdx.y == 3 builds the RoPE cos/sin table instead (QKV launch only).
#define GCK 32
#define WP  36
#define NPB 128
#define KSQ 16
#define KSO 32

__global__ void __launch_bounds__(256) mma_gemm_kernel(
                                   const float* __restrict__ X,
                                   const float* __restrict__ W0,
                                   const float* __restrict__ W1,
                                   const float* __restrict__ W2,
                                   int klen)
{
    if (blockIdx.y == 3) {
        // RoPE table: pos in [0,1024), j in [0,64)
        int idx = (blockIdx.x * gridDim.z + blockIdx.z) * 256 + threadIdx.x;
        if (idx < MAXC * 64) {
            int pos = idx >> 6;
            int j   = idx & 63;
            float theta = powf(10000.0f, -(float)j / 64.0f);
            float mm = (float)pos * theta;
            float s, c;
            sincosf(mm, &s, &c);
            g_cos[idx] = c;
            g_sin[idx] = s;
        }
        return;
    }

    __shared__ float ws[2][NPB * WP];
    __shared__ float xs[2][BB * WP];
    const float* Xp = X ? X : g_ctx;
    const float* W  = (blockIdx.y == 0) ? W0 : (blockIdx.y == 1) ? W1 : W2;
    const int tid   = threadIdx.x;
    const int lane  = tid & 31;
    const int warp  = tid >> 5;
    const int gid   = lane >> 2;     // 0..7
    const int tig   = lane & 3;      // 0..3
    const int n0    = warp * 16;
    const int nbase = blockIdx.x * NPB;
    const int kbase = blockIdx.z * klen;
    const int ntiles = klen / GCK;

    const uint32_t ws_b = (uint32_t)__cvta_generic_to_shared(&ws[0][0]);
    const uint32_t xs_b = (uint32_t)__cvta_generic_to_shared(&xs[0][0]);
    const uint32_t ws_sz = NPB * WP * 4;
    const uint32_t xs_sz = BB * WP * 4;

    auto stage = [&](int t) {
        const int buf = t & 1;
        const int k0 = kbase + t * GCK;
#pragma unroll
        for (int i = 0; i < 4; i++) {
            int idx = tid + i * 256;
            int r = idx >> 3, c2 = idx & 7;
            cpa16(ws_b + buf * ws_sz + (r * WP + 4 * c2) * 4,
                  &W[(size_t)(nbase + r) * DM + k0 + 4 * c2]);
        }
        {
            int r = tid >> 3, c2 = tid & 7;
            cpa16(xs_b + buf * xs_sz + (r * WP + 4 * c2) * 4,
                  &Xp[(size_t)r * DM + k0 + 4 * c2]);
        }
        asm volatile("cp.async.commit_group;");
    };

    float d[4][4];
#pragma unroll
    for (int i = 0; i < 4; i++)
#pragma unroll
        for (int j = 0; j < 4; j++) d[i][j] = 0.0f;

    stage(0);
    for (int t = 0; t < ntiles; t++) {
        if (t + 1 < ntiles) {
            stage(t + 1);
            asm volatile("cp.async.wait_group 1;");
        } else {
            asm volatile("cp.async.wait_group 0;");
        }
        __syncthreads();

        const int buf = t & 1;
        const float* xb = &xs[buf][0];
        const float* wb = &ws[buf][0];
#pragma unroll
        for (int k8 = 0; k8 < 4; k8++) {
            const int kk = k8 * 8;
            uint32_t A0[4], A1[4], B0[2], B1[2];
            A0[0] = f2tf(xb[(gid)      * WP + kk + tig]);
            A0[1] = f2tf(xb[(gid + 8)  * WP + kk + tig]);
            A0[2] = f2tf(xb[(gid)      * WP + kk + tig + 4]);
            A0[3] = f2tf(xb[(gid + 8)  * WP + kk + tig + 4]);
            A1[0] = f2tf(xb[(gid + 16) * WP + kk + tig]);
            A1[1] = f2tf(xb[(gid + 24) * WP + kk + tig]);
            A1[2] = f2tf(xb[(gid + 16) * WP + kk + tig + 4]);
            A1[3] = f2tf(xb[(gid + 24) * WP + kk + tig + 4]);
            B0[0] = f2tf(wb[(n0 + gid)     * WP + kk + tig]);
            B0[1] = f2tf(wb[(n0 + gid)     * WP + kk + tig + 4]);
            B1[0] = f2tf(wb[(n0 + 8 + gid) * WP + kk + tig]);
            B1[1] = f2tf(wb[(n0 + 8 + gid) * WP + kk + tig + 4]);
            mma8(d[0], A0, B0);
            mma8(d[1], A0, B1);
            mma8(d[2], A1, B0);
            mma8(d[3], A1, B1);
        }
        __syncthreads();
    }

    const int slab = (blockIdx.y * gridDim.z + blockIdx.z) * (BB * DM);
#pragma unroll
    for (int mi = 0; mi < 2; mi++)
#pragma unroll
        for (int ni = 0; ni < 2; ni++) {
            const float* dd = d[mi * 2 + ni];
            int ncol = nbase + n0 + ni * 8 + 2 * tig;
            int brow = gid + mi * 16;
            *(float2*)&g_part[slab + (size_t)brow * DM + ncol]       = make_float2(dd[0], dd[1]);
            *(float2*)&g_part[slab + (size_t)(brow + 8) * DM + ncol] = make_float2(dd[2], dd[3]);
        }
}

// reduce 32 k-split partials for the output projection into d_out
__global__ void o_reduce_kernel(float* __restrict__ out) {
    int i = blockIdx.x * 256 + threadIdx.x;   // 131072
    float v = 0.0f;
#pragma unroll
    for (int z = 0; z < KSO; z++) v += g_part[(size_t)z * (BB * DM) + i];
    out[i] = v;
}

// ---------------- attention: quarter-split x4; Q partial-reduce fused in prologue ----------------
__global__ void __launch_bounds__(256) attn_kernel(
                            const float* __restrict__ kcache,
                            const float* __restrict__ vcache,
                            const int* __restrict__ seqp)
{
    __shared__ __align__(16) float s_qr[DK];
    __shared__ __align__(16) float s_kn[DK];
    __shared__ __align__(16) float s_vn[DK];
    __shared__ float s_m[8];
    __shared__ float s_l[8];
    __shared__ float s_acc[8][DK + 4];

    const int h = blockIdx.x, b = blockIdx.y, zq = blockIdx.z;
    const int tid  = threadIdx.x;
    const int lane = tid & 31;
    const int warp = tid >> 5;

    const int seq = *seqp;
    int L, ii;
    if (seq < MAXC) { L = seq + 1; ii = seq; }
    else            { L = MAXC;    ii = SINK + (seq - SINK) % WINDOW; }
    const int qpos = L - 1;
    const int bh = b * HH + h;
    const int cbeg = zq << 8;
    const int cend = min(L, cbeg + 256);

    // ---- prologue: reduce Q (all blocks) and K/V (z==0 only) from GEMM partials ----
    if (tid < DK) {
        const size_t base = (size_t)b * DM + h * DK + tid;
        float vq = 0.0f;
#pragma unroll
        for (int z = 0; z < KSQ; z++) vq += g_part[(size_t)z * (BB * DM) + base];
        s_qr[tid] = vq;
        if (zq == 0) {
            float vk = 0.0f, vv = 0.0f;
#pragma unroll
            for (int z = 0; z < KSQ; z++) {
                vk += g_part[(size_t)(KSQ + z)     * (BB * DM) + base];
                vv += g_part[(size_t)(2 * KSQ + z) * (BB * DM) + base];
            }
            s_kn[tid] = vk;
            s_vn[tid] = vv;
        }
    }
    __syncthreads();
    if (tid < DK) {
        int j = tid & 63;
        float q0 = s_qr[tid];
        float flip = (tid < 64) ? -s_qr[tid + 64] : s_qr[tid - 64];
        float c = g_cos[qpos * 64 + j];
        float s = g_sin[qpos * 64 + j];
        s_acc[0][tid] = (q0 * c + flip * s) * 0.08838834764831843f;  // staging
    }
    __syncthreads();
    if (tid < DK) s_qr[tid] = s_acc[0][tid];
    __syncthreads();

    const float4 q4 = ((const float4*)s_qr)[lane];
    const float  sgn = (lane < 16) ? -1.0f : 1.0f;
    const int    j16 = lane & 15;
    const float* kbp  = kcache + (size_t)bh * MAXC * DK;
    const float* vbp  = vcache + (size_t)bh * MAXC * DK;

    // ---- init online softmax; z==0 warp 0 seeds with the inserted slot (RoPE pos == qpos) ----
    float m, l;
    float4 a;
    if (warp == 0 && zq == 0) {
        float4 kn = ((const float4*)s_kn)[lane];
        float4 vn = ((const float4*)s_vn)[lane];
        float4 cs = ((const float4*)(g_cos + qpos * 64))[j16];
        float4 sn = ((const float4*)(g_sin + qpos * 64))[j16];
        float fx = sgn * __shfl_xor_sync(0xffffffffu, kn.x, 16);
        float fy = sgn * __shfl_xor_sync(0xffffffffu, kn.y, 16);
        float fz = sgn * __shfl_xor_sync(0xffffffffu, kn.z, 16);
        float fw = sgn * __shfl_xor_sync(0xffffffffu, kn.w, 16);
        float d = q4.x * (kn.x * cs.x + fx * sn.x) + q4.y * (kn.y * cs.y + fy * sn.y)
                + q4.z * (kn.z * cs.z + fz * sn.z) + q4.w * (kn.w * cs.w + fw * sn.w);
#pragma unroll
        for (int o = 16; o; o >>= 1) d += __shfl_xor_sync(0xffffffffu, d, o);
        m = d; l = 1.0f; a = vn;
    } else {
        m = -1e30f; l = 0.0f; a = make_float4(0.f, 0.f, 0.f, 0.f);
    }

    int c = cbeg + warp;
    for (; c + 8 < cend; c += 16) {
        const int cA = c, cB = c + 8;
        float4 kA = __ldcs((const float4*)(kbp + (size_t)cA * DK) + lane);
        float4 kB = __ldcs((const float4*)(kbp + (size_t)cB * DK) + lane);
        float4 vA = __ldcs((const float4*)(vbp + (size_t)cA * DK) + lane);
        float4 vB = __ldcs((const float4*)(vbp + (size_t)cB * DK) + lane);
        int pA, pB;
        if (seq < MAXC) { pA = cA; pB = cB; }
        else {
            pA = (cA < SINK) ? cA : (cA > ii) ? (SINK + cA - ii - 1) : (cA + (MAXC - 1 - ii));
            pB = (cB < SINK) ? cB : (cB > ii) ? (SINK + cB - ii - 1) : (cB + (MAXC - 1 - ii));
        }
        float4 csA = ((const float4*)(g_cos + pA * 64))[j16];
        float4 snA = ((const float4*)(g_sin + pA * 64))[j16];
        float4 csB = ((const float4*)(g_cos + pB * 64))[j16];
        float4 snB = ((const float4*)(g_sin + pB * 64))[j16];
        float dA, dB;
        {
            float fx = sgn * __shfl_xor_sync(0xffffffffu, kA.x, 16);
            float fy = sgn * __shfl_xor_sync(0xffffffffu, kA.y, 16);
            float fz = sgn * __shfl_xor_sync(0xffffffffu, kA.z, 16);
            float fw = sgn * __shfl_xor_sync(0xffffffffu, kA.w, 16);
            dA = q4.x * (kA.x * csA.x + fx * snA.x) + q4.y * (kA.y * csA.y + fy * snA.y)
               + q4.z * (kA.z * csA.z + fz * snA.z) + q4.w * (kA.w * csA.w + fw * snA.w);
        }
        {
            float fx = sgn * __shfl_xor_sync(0xffffffffu, kB.x, 16);
            float fy = sgn * __shfl_xor_sync(0xffffffffu, kB.y, 16);
            float fz = sgn * __shfl_xor_sync(0xffffffffu, kB.z, 16);
            float fw = sgn * __shfl_xor_sync(0xffffffffu, kB.w, 16);
            dB = q4.x * (kB.x * csB.x + fx * snB.x) + q4.y * (kB.y * csB.y + fy * snB.y)
               + q4.z * (kB.z * csB.z + fz * snB.z) + q4.w * (kB.w * csB.w + fw * snB.w);
        }
#pragma unroll
        for (int o = 16; o; o >>= 1) {
            dA += __shfl_xor_sync(0xffffffffu, dA, o);
            dB += __shfl_xor_sync(0xffffffffu, dB, o);
        }
        const bool skA = (cA == ii), skB = (cB == ii);
        if (skA) dA = -1e30f;
        if (skB) dB = -1e30f;
        float mn = fmaxf(m, fmaxf(dA, dB));
        float sc = __expf(m - mn);
        float eA = skA ? 0.0f : __expf(dA - mn);
        float eB = skB ? 0.0f : __expf(dB - mn);
        l = l * sc + eA + eB;
        a.x = a.x * sc + eA * vA.x + eB * vB.x;
        a.y = a.y * sc + eA * vA.y + eB * vB.y;
        a.z = a.z * sc + eA * vA.z + eB * vB.z;
        a.w = a.w * sc + eA * vA.w + eB * vB.w;
        m = mn;
    }
    for (; c < cend; c += 8) {
        float4 kv = __ldcs((const float4*)(kbp + (size_t)c * DK) + lane);
        float4 vv = __ldcs((const float4*)(vbp + (size_t)c * DK) + lane);
        int pos;
        if (seq < MAXC) pos = c;
        else pos = (c < SINK) ? c
                 : (c > ii)   ? (SINK + c - ii - 1)
                              : (c + (MAXC - 1 - ii));
        float4 cs = ((const float4*)(g_cos + pos * 64))[j16];
        float4 sn = ((const float4*)(g_sin + pos * 64))[j16];
        float fx = sgn * __shfl_xor_sync(0xffffffffu, kv.x, 16);
        float fy = sgn * __shfl_xor_sync(0xffffffffu, kv.y, 16);
        float fz = sgn * __shfl_xor_sync(0xffffffffu, kv.z, 16);
        float fw = sgn * __shfl_xor_sync(0xffffffffu, kv.w, 16);
        float d = q4.x * (kv.x * cs.x + fx * sn.x) + q4.y * (kv.y * cs.y + fy * sn.y)
                + q4.z * (kv.z * cs.z + fz * sn.z) + q4.w * (kv.w * cs.w + fw * sn.w);
#pragma unroll
        for (int o = 16; o; o >>= 1) d += __shfl_xor_sync(0xffffffffu, d, o);
        const bool sk = (c == ii);
        if (sk) d = -1e30f;
        float mn = fmaxf(m, d);
        float sc = __expf(m - mn);
        float e  = sk ? 0.0f : __expf(d - mn);
        l = l * sc + e;
        a.x = a.x * sc + e * vv.x;
        a.y = a.y * sc + e * vv.y;
        a.z = a.z * sc + e * vv.z;
        a.w = a.w * sc + e * vv.w;
        m = mn;
    }

    // ---- combine 8 warps; emit raw per-quarter partial (M, den, val) ----
    if (lane == 0) { s_m[warp] = m; s_l[warp] = l; }
    *(float4*)&s_acc[warp][4 * lane] = a;
    __syncthreads();
    if (tid < DK) {
        float M = s_m[0];
#pragma unroll
        for (int w = 1; w < 8; w++) M = fmaxf(M, s_m[w]);
        float den = 0.0f, val = 0.0f;
#pragma unroll
        for (int w = 0; w < 8; w++) {
            float e = __expf(s_m[w] - M);
            den += e * s_l[w];
            val += e * s_acc[w][tid];
        }
        const int slot = bh * 4 + zq;
        if (tid == 0) { g_pm[slot] = M; g_pl[slot] = den; }
        g_pacc[(size_t)slot * DK + tid] = val;
    }
}

// ---------------- combine the 4 quarter partials into the context ----------------
__global__ void attn_combine_kernel() {
    const int bh  = blockIdx.x;              // 0..1023
    const int tid = threadIdx.x;             // 0..127
    float M = -1e30f;
#pragma unroll
    for (int z = 0; z < 4; z++) M = fmaxf(M, g_pm[bh * 4 + z]);
    float den = 0.0f, val = 0.0f;
#pragma unroll
    for (int z = 0; z < 4; z++) {
        float e = __expf(g_pm[bh * 4 + z] - M);
        den += e * g_pl[bh * 4 + z];
        val += e * g_pacc[(size_t)(bh * 4 + z) * DK + tid];
    }
    g_ctx[bh * DK + tid] = val / den;
}

// ---------------- launch ----------------
extern "C" void kernel_launch(void* const* d_in, const int* in_sizes, int n_in,
                              void* d_out, int out_size)
{
    const float* x_new   = (const float*)d_in[0];
    const float* k_cache = (const float*)d_in[1];
    const float* v_cache = (const float*)d_in[2];
    const float* W_Q     = (const float*)d_in[3];
    const float* W_K     = (const float*)d_in[4];
    const float* W_V     = (const float*)d_in[5];
    const float* W_O     = (const float*)d_in[6];
    const int*   seq_len = (const int*)  d_in[7];
    float* out = (float*)d_out;

    // 1. QKV projections (y=0..2) + RoPE table (y=3 slice): 16 k-splits of 256
    mma_gemm_kernel<<<dim3(DM / NPB, 4, KSQ), 256>>>(x_new, W_Q, W_K, W_V, DM / KSQ);

    // 2. attention: quarter-split x4, Q-reduce fused in prologue; then combine
    attn_kernel<<<dim3(HH, BB, 4), 256>>>(k_cache, v_cache, seq_len);
    attn_combine_kernel<<<BB * HH, DK>>>();

    // 3. output projection: tf32 MMA, 1 weight x 32 k-splits of 128, reduce into d_out
    mma_gemm_kernel<<<dim3(DM / NPB, 1, KSO), 256>>>(nullptr, W_O, W_O, W_O, DM / KSO);
    o_reduce_kernel<<<(BB * DM) / 256, 256>>>(out);
}